// round 4
// baseline (speedup 1.0000x reference)
#include <cuda_runtime.h>
#include <math.h>

#define NTOK 4096
#define DM   1024
#define DFF  2816
#define NEXP 8
#define NSEG 9            // 8 routed experts + 1 shared expert segment
#define SEG  4096         // max rows per segment

// ---------------- scratch (device globals; allocation-free) ----------------
__device__ float g_xnorm[(size_t)NTOK * DM];
__device__ int   g_cnt[NEXP];
__device__ int   g_rows[NEXP * SEG];                 // token id per (expert,slot)
__device__ float g_rw[NSEG * SEG];                   // combine weight per slot
__device__ int   g_pos[NTOK * 2];                    // flat slot index for each token's top-2
__device__ float g_h1[(size_t)NSEG * SEG * DFF];     // up-proj 1 (later holds gelu(h1)*h3)
__device__ float g_h3[(size_t)NSEG * SEG * DFF];     // up-proj 3
__device__ float g_orow[(size_t)NSEG * SEG * DM];    // down-proj rows

// ---------------- reset ----------------
__global__ void k_reset() {
    if (threadIdx.x < NEXP) g_cnt[threadIdx.x] = 0;
}

// ---------------- RMSNorm + gating + routing ----------------
__global__ void k_rms_gate(const float* __restrict__ x, const float* __restrict__ gw) {
    __shared__ float xs[DM];
    __shared__ float red[8];
    __shared__ float logits[NEXP];
    __shared__ float s_scale;

    int t = blockIdx.x, tid = threadIdx.x;
    const float* xr = x + (size_t)t * DM;

    float v[4];
    float ss = 0.f;
#pragma unroll
    for (int i = 0; i < 4; i++) { v[i] = xr[tid + 256 * i]; ss += v[i] * v[i]; }
#pragma unroll
    for (int o = 16; o; o >>= 1) ss += __shfl_xor_sync(0xffffffffu, ss, o);
    if ((tid & 31) == 0) red[tid >> 5] = ss;
    __syncthreads();
    if (tid == 0) {
        float s = 0.f;
#pragma unroll
        for (int i = 0; i < 8; i++) s += red[i];
        s_scale = rsqrtf(s / (float)DM + 1e-6f);
    }
    __syncthreads();
    float sc = s_scale;
#pragma unroll
    for (int i = 0; i < 4; i++) {
        float y = v[i] * sc;
        xs[tid + 256 * i] = y;
        g_xnorm[(size_t)t * DM + tid + 256 * i] = y;
    }
    __syncthreads();

    // gate logits: warp e computes dot(x_norm, gate_w[e])
    int w = tid >> 5, lane = tid & 31;
    const float* ge = gw + w * DM;
    float acc = 0.f;
    for (int i = lane; i < DM; i += 32) acc += xs[i] * ge[i];
#pragma unroll
    for (int o = 16; o; o >>= 1) acc += __shfl_xor_sync(0xffffffffu, acc, o);
    if (lane == 0) logits[w] = acc;
    __syncthreads();

    if (tid == 0) {
        // top-2 (first-occurrence tie-break matches jax top_k)
        int b0 = 0; float l0 = logits[0];
        for (int e = 1; e < NEXP; e++) if (logits[e] > l0) { l0 = logits[e]; b0 = e; }
        int b1 = -1; float l1 = -1e30f;
        for (int e = 0; e < NEXP; e++) if (e != b0 && logits[e] > l1) { l1 = logits[e]; b1 = e; }
        // renormalized top-2 softmax weights
        float w0 = 1.f / (1.f + expf(l1 - l0));
        float w1v = 1.f - w0;
        int s0 = atomicAdd(&g_cnt[b0], 1);
        g_rows[b0 * SEG + s0] = t; g_rw[b0 * SEG + s0] = w0;  g_pos[t * 2 + 0] = b0 * SEG + s0;
        int s1 = atomicAdd(&g_cnt[b1], 1);
        g_rows[b1 * SEG + s1] = t; g_rw[b1 * SEG + s1] = w1v; g_pos[t * 2 + 1] = b1 * SEG + s1;
    }
}

// ---------------- GEMM: C = A * B^T (NT), 128x128x16 tile, 8x8/thread ----------------
// MODE 0: up-proj with w1 (A = gathered x_norm, K=DM, N=DFF, C = g_h1)
// MODE 1: up-proj with w3 (same, C = g_h3)
// MODE 2: down-proj       (A = g_h1 rows, K=DFF, N=DM, C = g_orow)
template <int MODE>
__global__ __launch_bounds__(256, 2)
void k_gemm(const float* __restrict__ Bex, const float* __restrict__ Bsh) {
    constexpr int K = (MODE == 2) ? DFF : DM;
    constexpr int N = (MODE == 2) ? DM  : DFF;
    constexpr bool GATHER = (MODE != 2);

    int e = blockIdx.z;
    int cnt = (e == 8) ? SEG : g_cnt[e];
    int m0 = blockIdx.y * 128;
    if (m0 >= cnt) return;
    int n0 = blockIdx.x * 128;

    const float* B = (e == 8) ? Bsh : (Bex + (size_t)e * N * K);
    float* C = (MODE == 0) ? g_h1 : (MODE == 1) ? g_h3 : g_orow;

    __shared__ float As[16][132];
    __shared__ float Bs[16][132];
    __shared__ int rowtok[128];

    int tid = threadIdx.x;
    if (GATHER) {
        if (tid < 128) {
            int r = m0 + tid;
            int tok;
            if (e == 8) tok = r;
            else tok = (r < cnt) ? g_rows[e * SEG + r] : g_rows[e * SEG];
            rowtok[tid] = tok;
        }
        __syncthreads();
    }

    float accv[8][8];
#pragma unroll
    for (int i = 0; i < 8; i++)
#pragma unroll
        for (int j = 0; j < 8; j++) accv[i][j] = 0.f;

    int ty = tid >> 4, tx = tid & 15;

    for (int k0 = 0; k0 < K; k0 += 16) {
#pragma unroll
        for (int v = 0; v < 2; v++) {
            int i = tid + 256 * v;
            int row = i >> 2;
            int kv = (i & 3) * 4;
            const float* asrc;
            if (GATHER) {
                asrc = g_xnorm + (size_t)rowtok[row] * K + k0 + kv;
            } else {
                int r = m0 + row;
                int rr = (r < cnt) ? r : 0;
                asrc = g_h1 + ((size_t)e * SEG + rr) * K + k0 + kv;
            }
            float4 a = *(const float4*)asrc;
            As[kv + 0][row] = a.x; As[kv + 1][row] = a.y;
            As[kv + 2][row] = a.z; As[kv + 3][row] = a.w;
            const float* bsrc = B + (size_t)(n0 + row) * K + k0 + kv;
            float4 b = *(const float4*)bsrc;
            Bs[kv + 0][row] = b.x; Bs[kv + 1][row] = b.y;
            Bs[kv + 2][row] = b.z; Bs[kv + 3][row] = b.w;
        }
        __syncthreads();
#pragma unroll
        for (int k = 0; k < 16; k++) {
            float4 a0 = *(const float4*)&As[k][ty * 8];
            float4 a1 = *(const float4*)&As[k][ty * 8 + 4];
            float4 b0 = *(const float4*)&Bs[k][tx * 8];
            float4 b1 = *(const float4*)&Bs[k][tx * 8 + 4];
            float af[8] = {a0.x, a0.y, a0.z, a0.w, a1.x, a1.y, a1.z, a1.w};
            float bf[8] = {b0.x, b0.y, b0.z, b0.w, b1.x, b1.y, b1.z, b1.w};
#pragma unroll
            for (int i = 0; i < 8; i++)
#pragma unroll
                for (int j = 0; j < 8; j++) accv[i][j] += af[i] * bf[j];
        }
        __syncthreads();
    }

#pragma unroll
    for (int i = 0; i < 8; i++) {
        int r = m0 + ty * 8 + i;
        if (r < cnt) {
            float* dst = C + ((size_t)e * SEG + r) * N + n0 + tx * 8;
            float4 c0 = make_float4(accv[i][0], accv[i][1], accv[i][2], accv[i][3]);
            float4 c1 = make_float4(accv[i][4], accv[i][5], accv[i][6], accv[i][7]);
            *(float4*)dst = c0;
            *(float4*)(dst + 4) = c1;
        }
    }
}

// ---------------- activation: h1 = gelu_exact(h1) * h3 ----------------
__global__ void k_act() {
    int row = blockIdx.x;            // 0 .. NSEG*SEG-1
    int e = row >> 12;
    int r = row & (SEG - 1);
    int cnt = (e == 8) ? SEG : g_cnt[e];
    if (r >= cnt) return;
    size_t base = (size_t)row * DFF;
    for (int i = threadIdx.x; i < DFF; i += blockDim.x) {
        float h = g_h1[base + i];
        float g = 0.5f * h * (1.f + erff(h * 0.70710678118654752f));
        g_h1[base + i] = g * g_h3[base + i];
    }
}

// ---------------- combine: out = x + shared + w0*row0 + w1*row1 ----------------
__global__ void k_combine(const float* __restrict__ x, float* __restrict__ out) {
    int t = blockIdx.x;
    int p0 = g_pos[t * 2 + 0], p1 = g_pos[t * 2 + 1];
    float w0 = g_rw[p0], w1 = g_rw[p1];
    const float* xr = x + (size_t)t * DM;
    const float* sh = g_orow + ((size_t)8 * SEG + t) * DM;
    const float* r0 = g_orow + (size_t)p0 * DM;
    const float* r1 = g_orow + (size_t)p1 * DM;
    float* o = out + (size_t)t * DM;
    for (int i = threadIdx.x; i < DM; i += blockDim.x)
        o[i] = xr[i] + sh[i] + w0 * r0[i] + w1 * r1[i];
}

// ---------------- launch ----------------
extern "C" void kernel_launch(void* const* d_in, const int* in_sizes, int n_in,
                              void* d_out, int out_size) {
    const float* x   = (const float*)d_in[0];
    const float* gw  = (const float*)d_in[1];
    const float* w1  = (const float*)d_in[2];
    const float* w2  = (const float*)d_in[3];
    const float* w3  = (const float*)d_in[4];
    const float* sw1 = (const float*)d_in[5];
    const float* sw2 = (const float*)d_in[6];
    const float* sw3 = (const float*)d_in[7];
    float* out = (float*)d_out;

    k_reset<<<1, 32>>>();
    k_rms_gate<<<NTOK, 256>>>(x, gw);

    dim3 gup(DFF / 128, SEG / 128, NSEG);   // 22 x 32 x 9
    k_gemm<0><<<gup, 256>>>(w1, sw1);
    k_gemm<1><<<gup, 256>>>(w3, sw3);

    k_act<<<NSEG * SEG, 256>>>();

    dim3 gdn(DM / 128, SEG / 128, NSEG);    // 8 x 32 x 9
    k_gemm<2><<<gdn, 256>>>(w2, sw2);

    k_combine<<<NTOK, 256>>>(x, out);
}

// round 8
// speedup vs baseline: 2.0508x; 2.0508x over previous
#include <cuda_runtime.h>
#include <math.h>
#include <stdint.h>

#define NTOK 4096
#define DM   1024
#define DFF  2816
#define NEXP 8
#define NSEG 9
#define SEG  4096

#define PLANE  10240          // 128 rows * 80 bytes
#define STAGEB (4 * PLANE)    // Ah, Al, Bh, Bl
#define NSTAGE 3
#define SMEM_TOTAL (1024 + NSTAGE * STAGEB)

// ---------------- scratch (device globals; allocation-free) ----------------
__device__ int      g_cnt[NEXP];
__device__ int      g_rows[NEXP * SEG];
__device__ float    g_rw[NSEG * SEG];
__device__ int      g_pos[NTOK * 2];
__device__ uint16_t g_xnh[(size_t)NTOK * DM];
__device__ uint16_t g_xnl[(size_t)NTOK * DM];
__device__ uint16_t g_w1h[(size_t)NEXP * DFF * DM];
__device__ uint16_t g_w1l[(size_t)NEXP * DFF * DM];
__device__ uint16_t g_w3h[(size_t)NEXP * DFF * DM];
__device__ uint16_t g_w3l[(size_t)NEXP * DFF * DM];
__device__ uint16_t g_w2h[(size_t)NEXP * DM * DFF];
__device__ uint16_t g_w2l[(size_t)NEXP * DM * DFF];
__device__ uint16_t g_s1h[(size_t)DFF * DM];
__device__ uint16_t g_s1l[(size_t)DFF * DM];
__device__ uint16_t g_s3h[(size_t)DFF * DM];
__device__ uint16_t g_s3l[(size_t)DFF * DM];
__device__ uint16_t g_s2h[(size_t)DM * DFF];
__device__ uint16_t g_s2l[(size_t)DM * DFF];
__device__ float    g_h1[(size_t)NSEG * SEG * DFF];   // up1 output (pre-activation)
__device__ uint16_t g_hph[(size_t)NSEG * SEG * DFF];  // gelu(h1)*h3 hi
__device__ uint16_t g_hpl[(size_t)NSEG * SEG * DFF];  // gelu(h1)*h3 lo
__device__ float    g_orow[(size_t)NSEG * SEG * DM];  // down output rows

// ---------------- helpers ----------------
__device__ __forceinline__ uint32_t smem_u32(const void* p) {
    uint32_t a;
    asm("{ .reg .u64 t; cvta.to.shared.u64 t, %1; cvt.u32.u64 %0, t; }" : "=r"(a) : "l"(p));
    return a;
}
// round-to-nearest-even fp32 -> bf16 bits
__device__ __forceinline__ uint32_t bf16_rn_bits(float x) {
    uint32_t u = __float_as_uint(x);
    return (u + 0x7FFFu + ((u >> 16) & 1u)) >> 16;
}
#define CP_ASYNC16(dst, src) \
    asm volatile("cp.async.cg.shared.global [%0], [%1], 16;" :: "r"(dst), "l"(src))
#define CP_COMMIT()  asm volatile("cp.async.commit_group;" ::: "memory")
#define CP_WAIT2()   asm volatile("cp.async.wait_group 2;" ::: "memory")

__device__ __forceinline__ void mma16816(float* d, const uint32_t* a, const uint32_t* b) {
    asm volatile(
        "mma.sync.aligned.m16n8k16.row.col.f32.bf16.bf16.f32 "
        "{%0,%1,%2,%3}, {%4,%5,%6,%7}, {%8,%9}, {%0,%1,%2,%3};"
        : "+f"(d[0]), "+f"(d[1]), "+f"(d[2]), "+f"(d[3])
        : "r"(a[0]), "r"(a[1]), "r"(a[2]), "r"(a[3]), "r"(b[0]), "r"(b[1]));
}

// ---------------- reset ----------------
__global__ void k_reset() {
    if (threadIdx.x < NEXP) g_cnt[threadIdx.x] = 0;
}

// ---------------- weight pre-split: fp32 -> bf16 hi/lo planes ----------------
template <int W>
__global__ void k_split(const float* __restrict__ src, int n) {
    uint16_t* hi;
    uint16_t* lo;
    if (W == 0) { hi = g_w1h; lo = g_w1l; }
    else if (W == 1) { hi = g_w2h; lo = g_w2l; }
    else if (W == 2) { hi = g_w3h; lo = g_w3l; }
    else if (W == 3) { hi = g_s1h; lo = g_s1l; }
    else if (W == 4) { hi = g_s2h; lo = g_s2l; }
    else            { hi = g_s3h; lo = g_s3l; }
    int i4 = (blockIdx.x * 256 + threadIdx.x) * 4;
    if (i4 >= n) return;
    float4 v = *(const float4*)(src + i4);
    uint32_t h0 = bf16_rn_bits(v.x), h1 = bf16_rn_bits(v.y);
    uint32_t h2 = bf16_rn_bits(v.z), h3 = bf16_rn_bits(v.w);
    ushort4 hv = make_ushort4((uint16_t)h0, (uint16_t)h1, (uint16_t)h2, (uint16_t)h3);
    ushort4 lv = make_ushort4(
        (uint16_t)bf16_rn_bits(v.x - __uint_as_float(h0 << 16)),
        (uint16_t)bf16_rn_bits(v.y - __uint_as_float(h1 << 16)),
        (uint16_t)bf16_rn_bits(v.z - __uint_as_float(h2 << 16)),
        (uint16_t)bf16_rn_bits(v.w - __uint_as_float(h3 << 16)));
    *(ushort4*)(hi + i4) = hv;
    *(ushort4*)(lo + i4) = lv;
}

// ---------------- RMSNorm + gating + routing (writes x_norm hi/lo) ----------------
__global__ void k_rms_gate(const float* __restrict__ x, const float* __restrict__ gw) {
    __shared__ float xs[DM];
    __shared__ float red[8];
    __shared__ float logits[NEXP];
    __shared__ float s_scale;

    int t = blockIdx.x, tid = threadIdx.x;
    const float* xr = x + (size_t)t * DM;

    float v[4];
    float ss = 0.f;
#pragma unroll
    for (int i = 0; i < 4; i++) { v[i] = xr[tid + 256 * i]; ss += v[i] * v[i]; }
#pragma unroll
    for (int o = 16; o; o >>= 1) ss += __shfl_xor_sync(0xffffffffu, ss, o);
    if ((tid & 31) == 0) red[tid >> 5] = ss;
    __syncthreads();
    if (tid == 0) {
        float s = 0.f;
#pragma unroll
        for (int i = 0; i < 8; i++) s += red[i];
        s_scale = rsqrtf(s / (float)DM + 1e-6f);
    }
    __syncthreads();
    float sc = s_scale;
#pragma unroll
    for (int i = 0; i < 4; i++) {
        float y = v[i] * sc;
        xs[tid + 256 * i] = y;
        size_t idx = (size_t)t * DM + tid + 256 * i;
        uint32_t hb = bf16_rn_bits(y);
        g_xnh[idx] = (uint16_t)hb;
        g_xnl[idx] = (uint16_t)bf16_rn_bits(y - __uint_as_float(hb << 16));
    }
    __syncthreads();

    int w = tid >> 5, lane = tid & 31;
    const float* ge = gw + w * DM;
    float acc = 0.f;
    for (int i = lane; i < DM; i += 32) acc += xs[i] * ge[i];
#pragma unroll
    for (int o = 16; o; o >>= 1) acc += __shfl_xor_sync(0xffffffffu, acc, o);
    if (lane == 0) logits[w] = acc;
    __syncthreads();

    if (tid == 0) {
        int b0 = 0; float l0 = logits[0];
        for (int e = 1; e < NEXP; e++) if (logits[e] > l0) { l0 = logits[e]; b0 = e; }
        int b1 = -1; float l1 = -1e30f;
        for (int e = 0; e < NEXP; e++) if (e != b0 && logits[e] > l1) { l1 = logits[e]; b1 = e; }
        float w0 = 1.f / (1.f + expf(l1 - l0));
        float w1v = 1.f - w0;
        int s0 = atomicAdd(&g_cnt[b0], 1);
        g_rows[b0 * SEG + s0] = t; g_rw[b0 * SEG + s0] = w0;  g_pos[t * 2 + 0] = b0 * SEG + s0;
        int s1 = atomicAdd(&g_cnt[b1], 1);
        g_rows[b1 * SEG + s1] = t; g_rw[b1 * SEG + s1] = w1v; g_pos[t * 2 + 1] = b1 * SEG + s1;
    }
}

// ---------------- stage loader: pure cp.async from hi/lo planes ----------------
// Stage planes: 0=Ah 1=Al 2=Bh 3=Bl. Each plane: 128 rows x 32 bf16, 80B row stride.
template <int MODE, int K>
__device__ __forceinline__ void load_stage(uint32_t sbase, int stg, const int* rowtok,
                                           int e, int cnt, int m0, int n0,
                                           const uint16_t* Ah, const uint16_t* Al,
                                           const uint16_t* Bh, const uint16_t* Bl,
                                           int kc, int tid) {
    uint32_t stbase = sbase + 1024 + stg * STAGEB;
#pragma unroll
    for (int c = 0; c < 8; c++) {
        int i = tid + c * 256;        // 0..2047
        int plane = i >> 9;
        int j = i & 511;
        int row = j >> 2;
        int kq = (j & 3) * 8;         // element offset within 32-elem chunk
        const uint16_t* src;
        if (plane < 2) {
            const uint16_t* P = plane ? Al : Ah;
            size_t r;
            if (MODE < 2) {
                r = (size_t)rowtok[row];
            } else {
                int rr = m0 + row;
                if (rr >= cnt) rr = m0;
                r = (size_t)e * SEG + rr;
            }
            src = P + r * K + kc * 32 + kq;
        } else {
            const uint16_t* P = (plane == 2) ? Bh : Bl;
            src = P + (size_t)(n0 + row) * K + kc * 32 + kq;
        }
        uint32_t dst = stbase + plane * PLANE + row * 80 + (j & 3) * 16;
        CP_ASYNC16(dst, src);
    }
}

// ---------------- per-stage compute: 2 x k16 steps, 3-term split ----------------
__device__ __forceinline__ void compute_stage(const char* st, float acc[2][8][4],
                                              int lane, int wm, int wn) {
    int g = lane >> 2, tg = lane & 3;
    const char* Ahp = st;
    const char* Alp = st + PLANE;
    const char* Bhp = st + 2 * PLANE;
    const char* Blp = st + 3 * PLANE;
#pragma unroll
    for (int kk = 0; kk < 2; kk++) {
        int c0 = (kk * 16 + tg * 2) * 2;   // byte offset within row
        uint32_t ah[2][4], al[2][4];
#pragma unroll
        for (int mt = 0; mt < 2; mt++) {
            int rb = wm * 32 + mt * 16;
            ah[mt][0] = *(const uint32_t*)(Ahp + (rb + g) * 80 + c0);
            ah[mt][1] = *(const uint32_t*)(Ahp + (rb + g + 8) * 80 + c0);
            ah[mt][2] = *(const uint32_t*)(Ahp + (rb + g) * 80 + c0 + 16);
            ah[mt][3] = *(const uint32_t*)(Ahp + (rb + g + 8) * 80 + c0 + 16);
            al[mt][0] = *(const uint32_t*)(Alp + (rb + g) * 80 + c0);
            al[mt][1] = *(const uint32_t*)(Alp + (rb + g + 8) * 80 + c0);
            al[mt][2] = *(const uint32_t*)(Alp + (rb + g) * 80 + c0 + 16);
            al[mt][3] = *(const uint32_t*)(Alp + (rb + g + 8) * 80 + c0 + 16);
        }
        uint32_t bh[8][2], bl[8][2];
#pragma unroll
        for (int nt = 0; nt < 8; nt++) {
            int nr = wn * 64 + nt * 8 + g;
            bh[nt][0] = *(const uint32_t*)(Bhp + nr * 80 + c0);
            bh[nt][1] = *(const uint32_t*)(Bhp + nr * 80 + c0 + 16);
            bl[nt][0] = *(const uint32_t*)(Blp + nr * 80 + c0);
            bl[nt][1] = *(const uint32_t*)(Blp + nr * 80 + c0 + 16);
        }
#pragma unroll
        for (int mt = 0; mt < 2; mt++)
#pragma unroll
            for (int nt = 0; nt < 8; nt++) {
                mma16816(acc[mt][nt], ah[mt], bh[nt]);
                mma16816(acc[mt][nt], ah[mt], bl[nt]);
                mma16816(acc[mt][nt], al[mt], bh[nt]);
            }
    }
}

// ---------------- HMMA GEMM, 3-stage cp.async pipeline ----------------
// MODE 0: up1 (A = gathered x_norm, B = w1)  -> g_h1 fp32
// MODE 1: up3 (A = gathered x_norm, B = w3)  -> epi: gelu(g_h1)*d -> g_hph/g_hpl
// MODE 2: down (A = g_hp planes,    B = w2)  -> g_orow fp32
template <int MODE>
__global__ __launch_bounds__(256)
void k_gemm() {
    constexpr int K    = (MODE < 2) ? DM : DFF;
    constexpr int NOUT = (MODE < 2) ? DFF : DM;
    constexpr int NC   = K / 32;

    extern __shared__ char smem[];
    int e = blockIdx.z;
    int cnt = (e == 8) ? SEG : g_cnt[e];
    int m0 = blockIdx.y * 128;
    if (m0 >= cnt) return;
    int n0 = blockIdx.x * 128;

    const uint16_t *Ah, *Al, *Bh, *Bl;
    if (MODE == 0) {
        Bh = (e == 8) ? g_s1h : g_w1h + (size_t)e * NOUT * K;
        Bl = (e == 8) ? g_s1l : g_w1l + (size_t)e * NOUT * K;
    } else if (MODE == 1) {
        Bh = (e == 8) ? g_s3h : g_w3h + (size_t)e * NOUT * K;
        Bl = (e == 8) ? g_s3l : g_w3l + (size_t)e * NOUT * K;
    } else {
        Bh = (e == 8) ? g_s2h : g_w2h + (size_t)e * NOUT * K;
        Bl = (e == 8) ? g_s2l : g_w2l + (size_t)e * NOUT * K;
    }
    Ah = (MODE < 2) ? g_xnh : g_hph;
    Al = (MODE < 2) ? g_xnl : g_hpl;

    int tid = threadIdx.x;
    int lane = tid & 31, w = tid >> 5;
    int wm = w & 3, wn = w >> 2;
    int* rowtok = (int*)smem;
    uint32_t sb = smem_u32(smem);

    if (MODE < 2 && tid < 128) {
        int r = m0 + tid;
        rowtok[tid] = (e == 8) ? r : ((r < cnt) ? g_rows[e * SEG + r] : g_rows[e * SEG]);
    }
    __syncthreads();

    load_stage<MODE, K>(sb, 0, rowtok, e, cnt, m0, n0, Ah, Al, Bh, Bl, 0, tid);
    CP_COMMIT();
    load_stage<MODE, K>(sb, 1, rowtok, e, cnt, m0, n0, Ah, Al, Bh, Bl, 1, tid);
    CP_COMMIT();

    float acc[2][8][4];
#pragma unroll
    for (int mt = 0; mt < 2; mt++)
#pragma unroll
        for (int nt = 0; nt < 8; nt++)
#pragma unroll
            for (int q = 0; q < 4; q++) acc[mt][nt][q] = 0.f;

    for (int kc = 0; kc < NC; kc++) {
        if (kc + 2 < NC)
            load_stage<MODE, K>(sb, (kc + 2) % NSTAGE, rowtok, e, cnt, m0, n0,
                                Ah, Al, Bh, Bl, kc + 2, tid);
        CP_COMMIT();
        CP_WAIT2();
        __syncthreads();
        compute_stage(smem + 1024 + (kc % NSTAGE) * STAGEB, acc, lane, wm, wn);
        __syncthreads();
    }

    // ---- epilogue ----
    int g = lane >> 2, tg = lane & 3;
#pragma unroll
    for (int mt = 0; mt < 2; mt++) {
#pragma unroll
        for (int rh = 0; rh < 2; rh++) {
            int row = wm * 32 + mt * 16 + g + rh * 8;
            int r = m0 + row;
            if (r >= cnt) continue;
            size_t rb = ((size_t)e * SEG + r) * NOUT;
#pragma unroll
            for (int nt = 0; nt < 8; nt++) {
                int col = n0 + wn * 64 + nt * 8 + tg * 2;
                float d0 = acc[mt][nt][rh * 2 + 0];
                float d1 = acc[mt][nt][rh * 2 + 1];
                if (MODE == 0) {
                    *(float2*)(g_h1 + rb + col) = make_float2(d0, d1);
                } else if (MODE == 1) {
                    float2 h = *(const float2*)(g_h1 + rb + col);
                    float p0 = 0.5f * h.x * (1.f + erff(h.x * 0.70710678f)) * d0;
                    float p1 = 0.5f * h.y * (1.f + erff(h.y * 0.70710678f)) * d1;
                    uint32_t h0 = bf16_rn_bits(p0);
                    uint32_t h1b = bf16_rn_bits(p1);
                    uint32_t l0 = bf16_rn_bits(p0 - __uint_as_float(h0 << 16));
                    uint32_t l1 = bf16_rn_bits(p1 - __uint_as_float(h1b << 16));
                    *(uint32_t*)(g_hph + rb + col) = h0 | (h1b << 16);
                    *(uint32_t*)(g_hpl + rb + col) = l0 | (l1 << 16);
                } else {
                    *(float2*)(g_orow + rb + col) = make_float2(d0, d1);
                }
            }
        }
    }
}

// ---------------- combine: out = x + shared + w0*row0 + w1*row1 ----------------
__global__ void k_combine(const float* __restrict__ x, float* __restrict__ out) {
    int t = blockIdx.x;
    int p0 = g_pos[t * 2 + 0], p1 = g_pos[t * 2 + 1];
    float w0 = g_rw[p0], w1 = g_rw[p1];
    const float* xr = x + (size_t)t * DM;
    const float* sh = g_orow + ((size_t)8 * SEG + t) * DM;
    const float* r0 = g_orow + (size_t)p0 * DM;
    const float* r1 = g_orow + (size_t)p1 * DM;
    float* o = out + (size_t)t * DM;
    for (int i = threadIdx.x; i < DM; i += blockDim.x)
        o[i] = xr[i] + sh[i] + w0 * r0[i] + w1 * r1[i];
}

// ---------------- launch ----------------
extern "C" void kernel_launch(void* const* d_in, const int* in_sizes, int n_in,
                              void* d_out, int out_size) {
    const float* x   = (const float*)d_in[0];
    const float* gw  = (const float*)d_in[1];
    const float* w1  = (const float*)d_in[2];
    const float* w2  = (const float*)d_in[3];
    const float* w3  = (const float*)d_in[4];
    const float* sw1 = (const float*)d_in[5];
    const float* sw2 = (const float*)d_in[6];
    const float* sw3 = (const float*)d_in[7];
    float* out = (float*)d_out;

    cudaFuncSetAttribute(k_gemm<0>, cudaFuncAttributeMaxDynamicSharedMemorySize, SMEM_TOTAL);
    cudaFuncSetAttribute(k_gemm<1>, cudaFuncAttributeMaxDynamicSharedMemorySize, SMEM_TOTAL);
    cudaFuncSetAttribute(k_gemm<2>, cudaFuncAttributeMaxDynamicSharedMemorySize, SMEM_TOTAL);

    k_reset<<<1, 32>>>();

    const int nW = NEXP * DFF * DM;       // 23,068,672
    const int nS = DFF * DM;              //  2,883,584
    k_split<0><<<nW / 1024, 256>>>(w1, nW);
    k_split<1><<<nW / 1024, 256>>>(w2, nW);
    k_split<2><<<nW / 1024, 256>>>(w3, nW);
    k_split<3><<<nS / 1024, 256>>>(sw1, nS);
    k_split<4><<<nS / 1024, 256>>>(sw2, nS);
    k_split<5><<<nS / 1024, 256>>>(sw3, nS);

    k_rms_gate<<<NTOK, 256>>>(x, gw);

    dim3 gup(DFF / 128, SEG / 128, NSEG);   // 22 x 32 x 9
    k_gemm<0><<<gup, 256, SMEM_TOTAL>>>();
    k_gemm<1><<<gup, 256, SMEM_TOTAL>>>();

    dim3 gdn(DM / 128, SEG / 128, NSEG);    // 8 x 32 x 9
    k_gemm<2><<<gdn, 256, SMEM_TOTAL>>>();

    k_combine<<<NTOK, 256>>>(x, out);
}